// round 6
// baseline (speedup 1.0000x reference)
#include <cuda_runtime.h>

// BERTEmbedding: out[b,l,:] = token_table[seq[b,l],:]
//                           + mean_{g<cnt}(genre_table[gids[seq[b,l],g],:])
//                           + pos_table[l,:]
//
// R6: offload the genre gathers (largest LDG class) from the LSU/L1tex port
// to the shared-memory crossbar. Genre table (21 x 128 f32 = 10.5KB) is staged
// in smem once per CTA; each CTA processes 64 tokens (8 per warp) to amortize
// staging. Remaining LSU work per token: 6 LDG.128 + 1 STG.128.

#define NUM_TOKENS (256 * 200)
#define SEQ_L 200
#define MAX_G 8
#define N_GENRE 21
#define TOKENS_PER_WARP 8
#define BLOCK_THREADS 256
#define WARPS_PER_BLOCK (BLOCK_THREADS / 32)
#define TOKENS_PER_BLOCK (WARPS_PER_BLOCK * TOKENS_PER_WARP)   // 64
#define GRID_BLOCKS (NUM_TOKENS / TOKENS_PER_BLOCK)            // 800

__global__ __launch_bounds__(BLOCK_THREADS) void bert_embed_kernel(
    const int* __restrict__ seq,          // [256*200]
    const float4* __restrict__ tok_tab,   // [VOCAB,32]
    const float4* __restrict__ gen_tab,   // [21,32]
    const float4* __restrict__ pos_tab,   // [200,32]
    const int4* __restrict__ tgid,        // [VOCAB,8] as [VOCAB,2] int4
    const int* __restrict__ gcnt,         // [VOCAB]
    float4* __restrict__ out)             // [256*200,32]
{
    __shared__ float4 s_gen[N_GENRE * 32];   // 10.5 KB

    // Stage genre table into smem (672 float4; 256 threads -> 3 iters).
    for (int i = threadIdx.x; i < N_GENRE * 32; i += BLOCK_THREADS)
        s_gen[i] = __ldg(&gen_tab[i]);
    __syncthreads();

    const int lane = threadIdx.x & 31;
    const int wid  = threadIdx.x >> 5;
    // This warp owns tokens [base, base+8)
    const int base = (blockIdx.x * WARPS_PER_BLOCK + wid) * TOKENS_PER_WARP;

    // l for the first token; increments by 1 per token, wraps at 200.
    int l = base % SEQ_L;

    // Prefetch first seq index.
    int t_next = __ldg(&seq[base]);

    #pragma unroll
    for (int j = 0; j < TOKENS_PER_WARP; j++) {
        const int i = base + j;
        const int t = t_next;
        if (j + 1 < TOKENS_PER_WARP) t_next = __ldg(&seq[i + 1]);

        // Independent global loads (LSU), issued back-to-back.
        const int    cnt = __ldg(&gcnt[t]);          // warp-uniform
        const int4   ga  = __ldg(&tgid[t * 2]);      // warp-uniform
        const int4   gb  = __ldg(&tgid[t * 2 + 1]);  // warp-uniform
        const float4 tok = __ldg(&tok_tab[t * 32 + lane]);
        const float4 pos = __ldg(&pos_tab[l * 32 + lane]);

        const int gid[MAX_G] = {ga.x, ga.y, ga.z, ga.w, gb.x, gb.y, gb.z, gb.w};

        // Genre accumulation from smem (off the LSU port).
        float4 s = make_float4(0.f, 0.f, 0.f, 0.f);
        #pragma unroll
        for (int g = 0; g < MAX_G; g++) {
            if (g < cnt) {                            // warp-uniform predicate
                const float4 ge = s_gen[gid[g] * 32 + lane];
                s.x += ge.x; s.y += ge.y; s.z += ge.z; s.w += ge.w;
            }
        }

        const float inv = 1.0f / (float)cnt;
        float4 o;
        o.x = tok.x + pos.x + s.x * inv;
        o.y = tok.y + pos.y + s.y * inv;
        o.z = tok.z + pos.z + s.z * inv;
        o.w = tok.w + pos.w + s.w * inv;

        out[i * 32 + lane] = o;

        // advance l (wraps at most once since TOKENS_PER_WARP < SEQ_L)
        l++;
        if (l == SEQ_L) l = 0;
    }
}

extern "C" void kernel_launch(void* const* d_in, const int* in_sizes, int n_in,
                              void* d_out, int out_size) {
    const int*    seq     = (const int*)d_in[0];
    const float4* tok_tab = (const float4*)d_in[1];
    const float4* gen_tab = (const float4*)d_in[2];
    const float4* pos_tab = (const float4*)d_in[3];
    const int4*   tgid    = (const int4*)d_in[4];
    const int*    gcnt    = (const int*)d_in[5];
    float4*       out     = (float4*)d_out;

    bert_embed_kernel<<<GRID_BLOCKS, BLOCK_THREADS>>>(
        seq, tok_tab, gen_tab, pos_tab, tgid, gcnt, out);
}

// round 7
// speedup vs baseline: 1.1186x; 1.1186x over previous
#include <cuda_runtime.h>
#include <cstdint>

// BERTEmbedding: out[b,l,:] = token_table[seq[b,l],:]
//                           + mean_{g<cnt}(genre_table[gids[seq[b,l],g],:])
//                           + pos_table[l,:]
//
// R7: R1 compute layout (warp per token, lane k owns float4 at dim 4k,
// proven best occupancy) + block-level TMA bulk store. Warps stage their
// 512B output rows in smem; thread 0 issues one cp.async.bulk (4KB) per
// block. Removes STG.128 (12-cyc LSU issue + 4 L1 wavefronts) from every
// warp's critical path and converts the write stream into contiguous 4KB
// bursts.

#define NUM_TOKENS (256 * 200)
#define SEQ_L 200
#define MAX_G 8
#define WARPS_PER_BLOCK 8
#define BLOCK_THREADS (WARPS_PER_BLOCK * 32)
#define GRID_BLOCKS (NUM_TOKENS / WARPS_PER_BLOCK)   // 6400
#define TILE_BYTES (WARPS_PER_BLOCK * 32 * 16)       // 4096

__device__ __forceinline__ uint32_t smem_u32(const void* p) {
    uint32_t a;
    asm("{ .reg .u64 t; cvta.to.shared.u64 t, %1; cvt.u32.u64 %0, t; }"
        : "=r"(a) : "l"(p));
    return a;
}

__global__ __launch_bounds__(BLOCK_THREADS) void bert_embed_kernel(
    const int* __restrict__ seq,          // [256*200]
    const float4* __restrict__ tok_tab,   // [VOCAB,32]
    const float4* __restrict__ gen_tab,   // [21,32]
    const float4* __restrict__ pos_tab,   // [200,32]
    const int4* __restrict__ tgid,        // [VOCAB,8] as [VOCAB,2] int4
    const int* __restrict__ gcnt,         // [VOCAB]
    float4* __restrict__ out)             // [256*200,32]
{
    __shared__ alignas(16) float4 s_out[WARPS_PER_BLOCK * 32];  // 4 KB

    const int wid  = threadIdx.x >> 5;
    const int lane = threadIdx.x & 31;
    const int i    = blockIdx.x * WARPS_PER_BLOCK + wid;   // token index

    const int l = i % SEQ_L;
    const int t = __ldg(&seq[i]);                 // warp-uniform

    // Independent level-2 loads, back-to-back for MLP.
    const int    cnt = __ldg(&gcnt[t]);           // warp-uniform
    const int4   ga  = __ldg(&tgid[t * 2]);       // warp-uniform
    const int4   gb  = __ldg(&tgid[t * 2 + 1]);   // warp-uniform
    const float4 tok = __ldg(&tok_tab[t * 32 + lane]);
    const float4 pos = __ldg(&pos_tab[l * 32 + lane]);

    const int gid[MAX_G] = {ga.x, ga.y, ga.z, ga.w, gb.x, gb.y, gb.z, gb.w};

    float4 s = make_float4(0.f, 0.f, 0.f, 0.f);
    #pragma unroll
    for (int g = 0; g < MAX_G; g++) {
        if (g < cnt) {                             // warp-uniform predicate
            const float4 ge = __ldg(&gen_tab[gid[g] * 32 + lane]);  // L1-hot
            s.x += ge.x; s.y += ge.y; s.z += ge.z; s.w += ge.w;
        }
    }

    const float inv = 1.0f / (float)cnt;
    float4 o;
    o.x = tok.x + pos.x + s.x * inv;
    o.y = tok.y + pos.y + s.y * inv;
    o.z = tok.z + pos.z + s.z * inv;
    o.w = tok.w + pos.w + s.w * inv;

    // Stage to smem (off the LSU store path).
    s_out[wid * 32 + lane] = o;
    __syncthreads();

    // One bulk TMA store for the whole block's 4KB tile.
    if (threadIdx.x == 0) {
        asm volatile("fence.proxy.async.shared::cta;" ::: "memory");
        char* gdst = reinterpret_cast<char*>(out) + (size_t)blockIdx.x * TILE_BYTES;
        const uint32_t ssrc = smem_u32(s_out);
        asm volatile(
            "cp.async.bulk.global.shared::cta.bulk_group [%0], [%1], %2;"
            :: "l"(gdst), "r"(ssrc), "r"(TILE_BYTES) : "memory");
        asm volatile("cp.async.bulk.commit_group;" ::: "memory");
        // Keep the CTA alive until the bulk engine has consumed smem.
        asm volatile("cp.async.bulk.wait_group.read 0;" ::: "memory");
    }
}

extern "C" void kernel_launch(void* const* d_in, const int* in_sizes, int n_in,
                              void* d_out, int out_size) {
    const int*    seq     = (const int*)d_in[0];
    const float4* tok_tab = (const float4*)d_in[1];
    const float4* gen_tab = (const float4*)d_in[2];
    const float4* pos_tab = (const float4*)d_in[3];
    const int4*   tgid    = (const int4*)d_in[4];
    const int*    gcnt    = (const int*)d_in[5];
    float4*       out     = (float4*)d_out;

    bert_embed_kernel<<<GRID_BLOCKS, BLOCK_THREADS>>>(
        seq, tok_tab, gen_tab, pos_tab, tgid, gcnt, out);
}

// round 8
// speedup vs baseline: 1.1210x; 1.0021x over previous
#include <cuda_runtime.h>

// BERTEmbedding: out[b,l,:] = token_table[seq[b,l],:]
//                           + mean_{g<cnt}(genre_table[gids[seq[b,l],g],:])
//                           + pos_table[l,:]
//
// R8: minimize issued instructions per token.
//  - warp handles 4 tokens; lanes 0..3 preload seq/gcnt/1/cnt for all 4
//    tokens in parallel, broadcast via shfl (3 shfl/token vs ~15 slots of
//    uniform LDG + addressing + divide).
//  - genre loop runs exactly cnt iterations (warp-uniform trip count),
//    not 8 predicated unrolled ones.
//  - packed f32x2 math (add/fma.rn.f32x2 via inline PTX).
//  - pointer-increment addressing.
// Grid: 12800 warps = 1600 CTAs x 8 warps -> 64 warps/SM (one full wave+).

#define NUM_TOKENS (256 * 200)
#define SEQ_L 200
#define MAX_G 8
#define TOK_PER_WARP 4
#define BLOCK_THREADS 256
#define WARPS_TOTAL (NUM_TOKENS / TOK_PER_WARP)            // 12800
#define GRID_BLOCKS (WARPS_TOTAL / (BLOCK_THREADS / 32))   // 1600

typedef unsigned long long u64;

__device__ __forceinline__ u64 addx2(u64 a, u64 b) {
    u64 r; asm("add.rn.f32x2 %0, %1, %2;" : "=l"(r) : "l"(a), "l"(b)); return r;
}
__device__ __forceinline__ u64 fmax2(u64 a, u64 b, u64 c) {
    u64 r; asm("fma.rn.f32x2 %0, %1, %2, %3;" : "=l"(r) : "l"(a), "l"(b), "l"(c)); return r;
}
__device__ __forceinline__ u64 pack2(float lo, float hi) {
    u64 r; asm("mov.b64 %0, {%1, %2};" : "=l"(r) : "f"(lo), "f"(hi)); return r;
}

__global__ __launch_bounds__(BLOCK_THREADS) void bert_embed_kernel(
    const int* __restrict__ seq,              // [256*200]
    const ulonglong2* __restrict__ tok_tab,   // [VOCAB,32] 16B granules
    const ulonglong2* __restrict__ gen_tab,   // [21,32]
    const ulonglong2* __restrict__ pos_tab,   // [200,32]
    const int* __restrict__ tgid,             // [VOCAB,8]
    const int* __restrict__ gcnt,             // [VOCAB]
    ulonglong2* __restrict__ out)             // [256*200,32]
{
    const int lane = threadIdx.x & 31;
    const int warp = (blockIdx.x * BLOCK_THREADS + threadIdx.x) >> 5;
    const int base = warp * TOK_PER_WARP;

    // ---- lane-parallel metadata preload (lanes 0..3 carry real data) ----
    const int pidx  = base + (lane & (TOK_PER_WARP - 1));
    const int t_pre = __ldg(&seq[pidx]);
    const int c_pre = __ldg(&gcnt[t_pre]);
    const float inv_pre = 1.0f / (float)c_pre;   // amortized over 4 tokens

    int l = base % SEQ_L;                        // consecutive, wraps once max
    const ulonglong2* prow_out_base = out;       // silence unused warnings

    ulonglong2* po = out + (size_t)base * 32 + lane;

    #pragma unroll
    for (int j = 0; j < TOK_PER_WARP; j++) {
        const int   t   = __shfl_sync(0xffffffffu, t_pre, j);
        const int   cnt = __shfl_sync(0xffffffffu, c_pre, j);
        const float inv = __shfl_sync(0xffffffffu, inv_pre, j);

        // Independent gathers for this token.
        const ulonglong2 tok = __ldg(&tok_tab[(size_t)t * 32 + lane]);
        const ulonglong2 pos = __ldg(&pos_tab[l * 32 + lane]);
        const int* grow = &tgid[t * MAX_G];

        u64 s01 = 0, s23 = 0;                    // packed {0,0}
        for (int g = 0; g < cnt; g++) {          // warp-uniform trip count
            const int gid = __ldg(&grow[g]);     // scalar uniform, L1-hot
            const ulonglong2 ge = __ldg(&gen_tab[gid * 32 + lane]); // L1-hot
            s01 = addx2(s01, ge.x);
            s23 = addx2(s23, ge.y);
        }

        const u64 inv2 = pack2(inv, inv);
        ulonglong2 o;
        o.x = fmax2(s01, inv2, addx2(tok.x, pos.x));
        o.y = fmax2(s23, inv2, addx2(tok.y, pos.y));
        *po = o;

        po += 32;
        l++;
        if (l == SEQ_L) l = 0;
    }
    (void)prow_out_base;
}

extern "C" void kernel_launch(void* const* d_in, const int* in_sizes, int n_in,
                              void* d_out, int out_size) {
    const int*        seq     = (const int*)d_in[0];
    const ulonglong2* tok_tab = (const ulonglong2*)d_in[1];
    const ulonglong2* gen_tab = (const ulonglong2*)d_in[2];
    const ulonglong2* pos_tab = (const ulonglong2*)d_in[3];
    const int*        tgid    = (const int*)d_in[4];
    const int*        gcnt    = (const int*)d_in[5];
    ulonglong2*       out     = (ulonglong2*)d_out;

    bert_embed_kernel<<<GRID_BLOCKS, BLOCK_THREADS>>>(
        seq, tok_tab, gen_tab, pos_tab, tgid, gcnt, out);
}

// round 10
// speedup vs baseline: 1.1404x; 1.0173x over previous
#include <cuda_runtime.h>
#include <cstdint>

// BERTEmbedding: out[b,l,:] = token_table[seq[b,l],:]
//                           + mean_{g<cnt}(genre_table[gids[seq[b,l],g],:])
//                           + pos_table[l,:]
//
// R10 (= R9 theory, fixed mechanics): L2 residency management.
// ptxas rejects .L2::evict_last directly on v4.f32 loads; use the
// createpolicy + .L2::cache_hint form instead.
//   - token-table loads:  ld.global.nc.L2::cache_hint with evict_last policy
//   - output stores:      st.global.cs (evict-first stream)
// Layout: warp per token, lane k owns float4 at dim 4k (best occupancy).

#define NUM_TOKENS (256 * 200)
#define SEQ_L 200
#define MAX_G 8

__device__ __forceinline__ uint64_t mk_evict_last_policy() {
    uint64_t pol;
    asm("createpolicy.fractional.L2::evict_last.b64 %0, 1.0;" : "=l"(pol));
    return pol;
}

__device__ __forceinline__ float4 ldg_hint(const float4* p, uint64_t pol) {
    float4 v;
    asm volatile("ld.global.nc.L2::cache_hint.v4.f32 {%0,%1,%2,%3}, [%4], %5;"
                 : "=f"(v.x), "=f"(v.y), "=f"(v.z), "=f"(v.w)
                 : "l"(p), "l"(pol));
    return v;
}

__device__ __forceinline__ void stg_streaming(float4* p, float4 v) {
    asm volatile("st.global.cs.v4.f32 [%0], {%1,%2,%3,%4};"
                 :: "l"(p), "f"(v.x), "f"(v.y), "f"(v.z), "f"(v.w) : "memory");
}

__global__ __launch_bounds__(256) void bert_embed_kernel(
    const int* __restrict__ seq,          // [256*200]
    const float4* __restrict__ tok_tab,   // [VOCAB,32]
    const float4* __restrict__ gen_tab,   // [21,32]
    const float4* __restrict__ pos_tab,   // [200,32]
    const int4* __restrict__ tgid,        // [VOCAB,8] as [VOCAB,2] int4
    const int* __restrict__ gcnt,         // [VOCAB]
    float4* __restrict__ out)             // [256*200,32]
{
    const int warp = (blockIdx.x * blockDim.x + threadIdx.x) >> 5;
    const int lane = threadIdx.x & 31;

    const uint64_t pol = mk_evict_last_policy();

    const int l = warp % SEQ_L;
    const int t = __ldg(&seq[warp]);               // warp-uniform

    // Independent level-2 loads, back-to-back for MLP.
    const int    cnt = __ldg(&gcnt[t]);            // warp-uniform
    const int4   ga  = __ldg(&tgid[t * 2]);        // warp-uniform
    const int4   gb  = __ldg(&tgid[t * 2 + 1]);    // warp-uniform
    const float4 tok = ldg_hint(&tok_tab[(size_t)t * 32 + lane], pol);  // pin in L2
    const float4 pos = __ldg(&pos_tab[l * 32 + lane]);

    const int gid[MAX_G] = {ga.x, ga.y, ga.z, ga.w, gb.x, gb.y, gb.z, gb.w};

    float4 s = make_float4(0.f, 0.f, 0.f, 0.f);
    #pragma unroll
    for (int g = 0; g < MAX_G; g++) {
        if (g < cnt) {                              // warp-uniform predicate
            const float4 ge = __ldg(&gen_tab[gid[g] * 32 + lane]);  // L1-hot
            s.x += ge.x; s.y += ge.y; s.z += ge.z; s.w += ge.w;
        }
    }

    const float inv = 1.0f / (float)cnt;
    float4 o;
    o.x = tok.x + pos.x + s.x * inv;
    o.y = tok.y + pos.y + s.y * inv;
    o.z = tok.z + pos.z + s.z * inv;
    o.w = tok.w + pos.w + s.w * inv;

    // Streaming store: evict-first, don't churn the table out of L2.
    stg_streaming(&out[(size_t)warp * 32 + lane], o);
}

extern "C" void kernel_launch(void* const* d_in, const int* in_sizes, int n_in,
                              void* d_out, int out_size) {
    const int*    seq     = (const int*)d_in[0];
    const float4* tok_tab = (const float4*)d_in[1];
    const float4* gen_tab = (const float4*)d_in[2];
    const float4* pos_tab = (const float4*)d_in[3];
    const int4*   tgid    = (const int4*)d_in[4];
    const int*    gcnt    = (const int*)d_in[5];
    float4*       out     = (float4*)d_out;

    bert_embed_kernel<<<NUM_TOKENS / 8, 256>>>(
        seq, tok_tab, gen_tab, pos_tab, tgid, gcnt, out);
}